// round 11
// baseline (speedup 1.0000x reference)
#include <cuda_runtime.h>
#include <cuda_bf16.h>
#include <cstdint>

#define N_NODES 50000
#define D 128
#define TILES 391            // ceil(50000/128)
#define NGEMM (TILES * 2)    // 782 gemm CTAs (128x64 each)

// ---------------- scratch (__device__ globals; alloc-free rule) ------------
__device__ float4 g_agg4[(size_t)N_NODES * (D / 4)];
__device__ int    g_cnt[N_NODES];
// W^T split: [128 n][256 k] bf16 hi/lo, row-major. 128*32 = 4096 uint4 each.
__device__ uint4  g_bhi16[4096];
__device__ uint4  g_blo16[4096];

// ---------------- GEMM geometry: 128x64 tile, K=128 per kernel -------------
#define SA  40                // A smem row stride (bf16): 32 + 8 pad
#define SBF 136               // B smem row stride (bf16): 128 + 8 pad
#define A_BYTES (128 * SA * 2)            // 10240
#define B_BYTES (64 * SBF * 2)            // 17408
#define OFF_A(buf) ((buf) * 2 * A_BYTES)  // hi +0, lo +A_BYTES
#define OFF_BH  (2 * 2 * A_BYTES)         // 40960
#define OFF_BL  (OFF_BH + B_BYTES)        // 58368
#define SM_TOT  (OFF_BL + B_BYTES)        // 75776

__device__ __forceinline__ uint32_t smem_u32(const void* p) {
    uint32_t a;
    asm("{ .reg .u64 t; cvta.to.shared.u64 t, %1; cvt.u32.u64 %0, t; }"
        : "=r"(a) : "l"(p));
    return a;
}

#define LDSM4(r0, r1, r2, r3, addr)                                          \
    asm volatile("ldmatrix.sync.aligned.m8n8.x4.shared.b16 {%0,%1,%2,%3}, [%4];" \
                 : "=r"(r0), "=r"(r1), "=r"(r2), "=r"(r3) : "r"(addr))

#define MMA(d, a, b)                                                          \
    asm volatile("mma.sync.aligned.m16n8k16.row.col.f32.bf16.bf16.f32 "       \
                 "{%0,%1,%2,%3}, {%4,%5,%6,%7}, {%8,%9}, {%0,%1,%2,%3};"      \
                 : "+f"((d)[0]), "+f"((d)[1]), "+f"((d)[2]), "+f"((d)[3])     \
                 : "r"((a)[0]), "r"((a)[1]), "r"((a)[2]), "r"((a)[3]),        \
                   "r"((b)[0]), "r"((b)[1]))

// ---------------------------------------------------------------------------
// Kernel 1: init — zero agg + counts AND build W^T bf16 hi/lo blobs
// ---------------------------------------------------------------------------
__global__ void k_init(const float* __restrict__ W) {
    size_t i = (size_t)blockIdx.x * blockDim.x + threadIdx.x;
    size_t stride = (size_t)gridDim.x * blockDim.x;
    size_t n4 = (size_t)N_NODES * (D / 4);
    float4 z = make_float4(0.f, 0.f, 0.f, 0.f);
    for (size_t j = i; j < n4; j += stride) g_agg4[j] = z;
    for (size_t j = i; j < (size_t)N_NODES; j += stride) g_cnt[j] = 0;

    for (size_t id = i; id < 128 * 32; id += stride) {
        int n  = (int)(id >> 5);
        int k0 = (int)(id & 31) * 8;
        unsigned short hi[8], lo[8];
#pragma unroll
        for (int j = 0; j < 8; j++) {
            float v = W[(size_t)(k0 + j) * 128 + n];      // W[k][n]
            __nv_bfloat16 h = __float2bfloat16(v);
            __nv_bfloat16 l = __float2bfloat16(v - __bfloat162float(h));
            hi[j] = __bfloat16_as_ushort(h);
            lo[j] = __bfloat16_as_ushort(l);
        }
        g_bhi16[n * 32 + (k0 >> 3)] = *reinterpret_cast<uint4*>(hi);
        g_blo16[n * 32 + (k0 >> 3)] = *reinterpret_cast<uint4*>(lo);
    }
}

// ---------------------------------------------------------------------------
// GEMM body (K=128 half). AGG=false: out = x @ W[0:128]  (write).
// AGG=true:  out += (agg * rinv) @ W[128:256]  (accumulate).
// CTA computes 128 rows x 64 cols. 3-term bf16 split.
// ---------------------------------------------------------------------------
template <bool AGG>
__device__ __forceinline__ void gemm_body(int tile, int nh,
                                          const float* __restrict__ x,
                                          float* __restrict__ out,
                                          char* smem, uint32_t sbase) {
    const int tid  = threadIdx.x;
    const int wid  = tid >> 5;
    const int lane = tid & 31;

    // ---- B half (64 n-rows, this kernel's K half) ----
    {
        const int kofs16 = AGG ? 16 : 0;     // uint4 offset into 256-k rows
        uint4* bh = reinterpret_cast<uint4*>(smem + OFF_BH);
        uint4* bl = reinterpret_cast<uint4*>(smem + OFF_BL);
        for (int i = tid; i < 1024; i += 256) {
            int row = i >> 4, c16 = i & 15;
            bh[row * 17 + c16] = g_bhi16[(64 * nh + row) * 32 + kofs16 + c16];
            bl[row * 17 + c16] = g_blo16[(64 * nh + row) * 32 + kofs16 + c16];
        }
    }

    // ---- A loader: thread -> row tid/2, 16 cols at (tid&1)*16 ----
    const int ar  = tid >> 1;
    const int acb = (tid & 1) * 16;
    const int gr  = tile * 128 + ar;
    const bool valid = gr < N_NODES;
    float prescale = 1.f;
    if (AGG) {
        prescale = 0.f;
        if (valid) {
            int c = g_cnt[gr];
            prescale = 1.0f / (float)(c > 0 ? c : 1);
        }
    }
    const float* abase = AGG ? reinterpret_cast<const float*>(g_agg4) + (size_t)gr * D
                             : x + (size_t)gr * D;

    float4 pre[4];
    auto preload = [&](int c) {
        const float* src = abase + c * 32 + acb;
        if (valid) {
#pragma unroll
            for (int j = 0; j < 4; j++) pre[j] = reinterpret_cast<const float4*>(src)[j];
        } else {
#pragma unroll
            for (int j = 0; j < 4; j++) pre[j] = make_float4(0.f, 0.f, 0.f, 0.f);
        }
    };
    auto store_chunk = [&](int buf) {
        uint4* dh = reinterpret_cast<uint4*>(smem + OFF_A(buf));
        uint4* dl = reinterpret_cast<uint4*>(smem + OFF_A(buf) + A_BYTES);
#pragma unroll
        for (int g = 0; g < 2; g++) {
            float f[8];
            *reinterpret_cast<float4*>(f)     = pre[2 * g];
            *reinterpret_cast<float4*>(f + 4) = pre[2 * g + 1];
            unsigned short hi[8], lo[8];
#pragma unroll
            for (int j = 0; j < 8; j++) {
                float v = AGG ? f[j] * prescale : f[j];
                __nv_bfloat16 h = __float2bfloat16(v);
                __nv_bfloat16 l = __float2bfloat16(v - __bfloat162float(h));
                hi[j] = __bfloat16_as_ushort(h);
                lo[j] = __bfloat16_as_ushort(l);
            }
            int idx = ar * 5 + (acb >> 3) + g;   // SA*2/16 = 5 uint4 per row
            dh[idx] = *reinterpret_cast<uint4*>(hi);
            dl[idx] = *reinterpret_cast<uint4*>(lo);
        }
    };

    preload(0);
    store_chunk(0);
    __syncthreads();

    const int rL   = (lane & 7) + ((lane >> 3) & 1) * 8;
    const int col8 = (lane >> 4) * 8;
    const uint32_t aBaseRow = (uint32_t)((16 * wid + rL) * SA + col8) * 2;
    const uint32_t bBase    = sbase + OFF_BH + (uint32_t)(rL * SBF + col8) * 2;

    float acc[8][4];
#pragma unroll
    for (int ni = 0; ni < 8; ni++)
#pragma unroll
        for (int q = 0; q < 4; q++) acc[ni][q] = 0.f;

    for (int c = 0; c < 4; c++) {
        if (c < 3) preload(c + 1);

        const uint32_t aHi = sbase + OFF_A(c & 1) + aBaseRow;
        const uint32_t aLo = aHi + A_BYTES;
        const uint32_t bC  = (uint32_t)c * 64;     // 32 bf16 = 64 B
#pragma unroll
        for (int ks = 0; ks < 2; ks++) {
            const uint32_t ko = ks * 32;
            uint32_t ahi[4], alo[4];
            LDSM4(ahi[0], ahi[1], ahi[2], ahi[3], aHi + ko);
            LDSM4(alo[0], alo[1], alo[2], alo[3], aLo + ko);
#pragma unroll
            for (int nb = 0; nb < 4; nb++) {
                uint32_t bhi0[2], bhi1[2], blo0[2], blo1[2];
                {
                    uint32_t t0, t1, t2, t3;
                    LDSM4(t0, t1, t2, t3, bBase + bC + ko + nb * 16 * SBF * 2);
                    bhi0[0] = t0; bhi0[1] = t2; bhi1[0] = t1; bhi1[1] = t3;
                    LDSM4(t0, t1, t2, t3, bBase + (OFF_BL - OFF_BH) + bC + ko + nb * 16 * SBF * 2);
                    blo0[0] = t0; blo0[1] = t2; blo1[0] = t1; blo1[1] = t3;
                }
                MMA(acc[2 * nb],     ahi, bhi0);
                MMA(acc[2 * nb],     ahi, blo0);
                MMA(acc[2 * nb],     alo, bhi0);
                MMA(acc[2 * nb + 1], ahi, bhi1);
                MMA(acc[2 * nb + 1], ahi, blo1);
                MMA(acc[2 * nb + 1], alo, bhi1);
            }
        }

        if (c < 3) store_chunk((c + 1) & 1);
        __syncthreads();
    }

    // ---- epilogue ----
    {
        int r0 = tile * 128 + 16 * wid + (lane >> 2);
        int r1 = r0 + 8;
#pragma unroll
        for (int ni = 0; ni < 8; ni++) {
            int colo = nh * 64 + 8 * ni + 2 * (lane & 3);
            if (r0 < N_NODES) {
                float2* p = reinterpret_cast<float2*>(out + (size_t)r0 * 128 + colo);
                if (AGG) { float2 o = *p; o.x += acc[ni][0]; o.y += acc[ni][1]; *p = o; }
                else     { *p = make_float2(acc[ni][0], acc[ni][1]); }
            }
            if (r1 < N_NODES) {
                float2* p = reinterpret_cast<float2*>(out + (size_t)r1 * 128 + colo);
                if (AGG) { float2 o = *p; o.x += acc[ni][2]; o.y += acc[ni][3]; *p = o; }
                else     { *p = make_float2(acc[ni][2], acc[ni][3]); }
            }
        }
    }
}

// ---------------------------------------------------------------------------
// Kernel 2 (phase 1, fused): even blocks = x-half GEMM, odd blocks = scatter.
// Interleaved bids put both workloads on every SM from wave 1; scatter is
// LTS-bound, GEMM is tensor-bound -> complementary resources.
// ---------------------------------------------------------------------------
template <typename IdxT>
__global__ void __launch_bounds__(256, 2)
k_phase1(const float* __restrict__ x, const IdxT* __restrict__ ei, int E,
         float* __restrict__ out) {
    extern __shared__ char smem[];
    const int bid = blockIdx.x;

    if ((bid & 1) == 0) {
        int g = bid >> 1;                 // [0, NGEMM)
        gemm_body<false>(g >> 1, g & 1, x, out, smem, smem_u32(smem));
    } else {
        // scatter CTA: contiguous per-warp edge chunks
        int sblk = bid >> 1;              // [0, NGEMM)
        int wid  = threadIdx.x >> 5;
        int lane = threadIdx.x & 31;
        int w    = sblk * 8 + wid;        // warp id among 8*NGEMM
        const int nW = NGEMM * 8;
        int chunk = (E + nW - 1) / nW;
        int e0 = w * chunk;
        int e1 = min(E, e0 + chunk);
        for (int e = e0; e < e1; e++) {
            int s = (int)ei[e];
            int t = (int)ei[(size_t)E + e];
            float4 m = reinterpret_cast<const float4*>(x + (size_t)s * D)[lane];
            float4* a = g_agg4 + (size_t)t * (D / 4) + lane;
            asm volatile("red.global.add.v4.f32 [%0], {%1, %2, %3, %4};"
                         :: "l"(a), "f"(m.x), "f"(m.y), "f"(m.z), "f"(m.w) : "memory");
            if (lane == 0) atomicAdd(&g_cnt[t], 1);
        }
    }
}

// ---------------------------------------------------------------------------
// Kernel 3 (phase 2): out += mean @ W[128:256]
// ---------------------------------------------------------------------------
__global__ void __launch_bounds__(256, 2)
k_gemm_agg(float* __restrict__ out) {
    extern __shared__ char smem[];
    int g = blockIdx.x;
    gemm_body<true>(g >> 1, g & 1, nullptr, out, smem, smem_u32(smem));
}

// ---------------------------------------------------------------------------
extern "C" void kernel_launch(void* const* d_in, const int* in_sizes, int n_in,
                              void* d_out, int out_size) {
    const float* x = (const float*)d_in[0];
    const float* W = (const float*)d_in[2];
    float* out = (float*)d_out;

    int nelem = in_sizes[1];
    int E; bool is64;
    if (nelem == 2 * 800000)      { E = 800000;    is64 = false; }
    else if (nelem == 4 * 800000) { E = 800000;    is64 = true;  }
    else                          { E = nelem / 2; is64 = false; }

    cudaFuncSetAttribute(k_phase1<int>,       cudaFuncAttributeMaxDynamicSharedMemorySize, SM_TOT);
    cudaFuncSetAttribute(k_phase1<long long>, cudaFuncAttributeMaxDynamicSharedMemorySize, SM_TOT);
    cudaFuncSetAttribute(k_gemm_agg,          cudaFuncAttributeMaxDynamicSharedMemorySize, SM_TOT);

    k_init<<<592, 256>>>(W);
    if (is64)
        k_phase1<long long><<<NGEMM * 2, 256, SM_TOT>>>(x, (const long long*)d_in[1], E, out);
    else
        k_phase1<int><<<NGEMM * 2, 256, SM_TOT>>>(x, (const int*)d_in[1], E, out);
    k_gemm_agg<<<NGEMM, 256, SM_TOT>>>(out);
}